// round 3
// baseline (speedup 1.0000x reference)
#include <cuda_runtime.h>
#include <cuda_bf16.h>

// CenterLoss: loss = sum_i clamp(||pred_i - centers[target_i]||^2, 1e-12, 1e12)
//             + batch*(num_classes-1)*1e-12
//
// pred:    [16384, 1024] f32   (16777216 elems)
// centers: [10000, 1024] f32   (10240000 elems)
// target:  [16384] int32       (JAX x64-disabled downcasts the requested int64)
// out:     [1] f32

#define BATCH 16384
#define NUM_CLASSES 10000
#define FEAT_DIM 1024
#define THREADS 256

__global__ void centerloss_init_kernel(float* out) {
    // masked-out entries contribute batch*(num_classes-1)*1e-12
    out[0] = (float)((double)BATCH * (double)(NUM_CLASSES - 1) * 1e-12);
}

__global__ __launch_bounds__(THREADS)
void centerloss_kernel(const float* __restrict__ pred,
                       const float* __restrict__ centers,
                       const int* __restrict__ target,
                       float* __restrict__ out) {
    const int row = blockIdx.x;
    const int tid = threadIdx.x;

    const int cls = target[row];

    // Each thread handles exactly one float4: 256 threads * 4 = 1024 elems.
    const float4* p4 = reinterpret_cast<const float4*>(pred + (size_t)row * FEAT_DIM);
    const float4* c4 = reinterpret_cast<const float4*>(centers + (size_t)cls * FEAT_DIM);

    float4 p = p4[tid];
    float4 c = __ldg(&c4[tid]);

    float d0 = p.x - c.x;
    float d1 = p.y - c.y;
    float d2 = p.z - c.z;
    float d3 = p.w - c.w;

    float sum = fmaf(d0, d0, fmaf(d1, d1, fmaf(d2, d2, d3 * d3)));

    // warp reduce
    #pragma unroll
    for (int off = 16; off > 0; off >>= 1)
        sum += __shfl_xor_sync(0xFFFFFFFFu, sum, off);

    __shared__ float warp_sums[THREADS / 32];
    const int wid = tid >> 5;
    const int lid = tid & 31;
    if (lid == 0) warp_sums[wid] = sum;
    __syncthreads();

    if (wid == 0) {
        float v = (lid < THREADS / 32) ? warp_sums[lid] : 0.0f;
        #pragma unroll
        for (int off = 4; off > 0; off >>= 1)
            v += __shfl_xor_sync(0xFFFFFFFFu, v, off);
        if (lid == 0) {
            // dist >= 0 always; clamp per reference semantics
            v = fminf(fmaxf(v, 1e-12f), 1e12f);
            atomicAdd(out, v);
        }
    }
}

extern "C" void kernel_launch(void* const* d_in, const int* in_sizes, int n_in,
                              void* d_out, int out_size) {
    // Identify inputs by element count (robust to metadata ordering).
    const float* pred    = nullptr;
    const float* centers = nullptr;
    const int*   target  = nullptr;
    for (int i = 0; i < n_in; i++) {
        if (in_sizes[i] == BATCH * FEAT_DIM)            pred    = (const float*)d_in[i];
        else if (in_sizes[i] == NUM_CLASSES * FEAT_DIM) centers = (const float*)d_in[i];
        else if (in_sizes[i] == BATCH)                  target  = (const int*)d_in[i];
    }
    float* out = (float*)d_out;

    centerloss_init_kernel<<<1, 1>>>(out);
    centerloss_kernel<<<BATCH, THREADS>>>(pred, centers, target, out);
}

// round 4
// speedup vs baseline: 1.8845x; 1.8845x over previous
#include <cuda_runtime.h>
#include <cuda_bf16.h>

// CenterLoss: loss = sum_i clamp(||pred_i - centers[target_i]||^2, 1e-12, 1e12)
//             + batch*(num_classes-1)*1e-12
//
// dist >= 0 always and ~O(2*FEAT_DIM) for N(0,1) data; the clamp can only
// change the total by < 1e-12 per row (total ~3e7), so we sum unclamped.
//
// pred:    [16384, 1024] f32
// centers: [10000, 1024] f32
// target:  [16384] int32
// out:     [1] f32

#define BATCH 16384
#define NUM_CLASSES 10000
#define FEAT_DIM 1024
#define THREADS 256
#define WARPS_PER_CTA (THREADS / 32)
#define GRID (BATCH / WARPS_PER_CTA)   // 2048 CTAs, one row per warp

__global__ void centerloss_init_kernel(float* out) {
    // masked-out entries contribute batch*(num_classes-1)*1e-12
    out[0] = (float)((double)BATCH * (double)(NUM_CLASSES - 1) * 1e-12);
}

__global__ __launch_bounds__(THREADS)
void centerloss_kernel(const float* __restrict__ pred,
                       const float* __restrict__ centers,
                       const int* __restrict__ target,
                       float* __restrict__ out) {
    const int tid  = threadIdx.x;
    const int wid  = tid >> 5;
    const int lane = tid & 31;
    const int row  = blockIdx.x * WARPS_PER_CTA + wid;

    const int cls = __ldg(&target[row]);

    const float4* p4 = reinterpret_cast<const float4*>(pred + (size_t)row * FEAT_DIM);
    const float4* c4 = reinterpret_cast<const float4*>(centers + (size_t)cls * FEAT_DIM);

    // 1024 floats / warp = 8 float4 per lane; fully unrolled -> 16 loads in flight.
    float4 p[8], c[8];
    #pragma unroll
    for (int i = 0; i < 8; i++) p[i] = p4[lane + 32 * i];
    #pragma unroll
    for (int i = 0; i < 8; i++) c[i] = __ldg(&c4[lane + 32 * i]);

    float acc = 0.0f;
    #pragma unroll
    for (int i = 0; i < 8; i++) {
        float d0 = p[i].x - c[i].x;
        float d1 = p[i].y - c[i].y;
        float d2 = p[i].z - c[i].z;
        float d3 = p[i].w - c[i].w;
        acc = fmaf(d0, d0, acc);
        acc = fmaf(d1, d1, acc);
        acc = fmaf(d2, d2, acc);
        acc = fmaf(d3, d3, acc);
    }

    // Single end-of-kernel reduction: warp -> CTA -> one atomic per CTA.
    #pragma unroll
    for (int off = 16; off > 0; off >>= 1)
        acc += __shfl_xor_sync(0xFFFFFFFFu, acc, off);

    __shared__ float warp_sums[WARPS_PER_CTA];
    if (lane == 0) warp_sums[wid] = acc;
    __syncthreads();

    if (wid == 0) {
        float v = (lane < WARPS_PER_CTA) ? warp_sums[lane] : 0.0f;
        #pragma unroll
        for (int off = 4; off > 0; off >>= 1)
            v += __shfl_xor_sync(0xFFFFFFFFu, v, off);
        if (lane == 0)
            atomicAdd(out, v);
    }
}

extern "C" void kernel_launch(void* const* d_in, const int* in_sizes, int n_in,
                              void* d_out, int out_size) {
    // Identify inputs by element count (robust to metadata ordering).
    const float* pred    = nullptr;
    const float* centers = nullptr;
    const int*   target  = nullptr;
    for (int i = 0; i < n_in; i++) {
        if (in_sizes[i] == BATCH * FEAT_DIM)            pred    = (const float*)d_in[i];
        else if (in_sizes[i] == NUM_CLASSES * FEAT_DIM) centers = (const float*)d_in[i];
        else if (in_sizes[i] == BATCH)                  target  = (const int*)d_in[i];
    }
    float* out = (float*)d_out;

    centerloss_init_kernel<<<1, 1>>>(out);
    centerloss_kernel<<<GRID, THREADS>>>(pred, centers, target, out);
}

// round 5
// speedup vs baseline: 2.1081x; 1.1186x over previous
#include <cuda_runtime.h>
#include <cuda_bf16.h>

// CenterLoss: loss = sum_i clamp(||pred_i - centers[target_i]||^2, 1e-12, 1e12)
//             + batch*(num_classes-1)*1e-12
//
// dist >= 0 always and ~O(2*FEAT_DIM) for N(0,1) data; the clamp can only
// change the total by < 1e-12 per row (total ~3e7), so we sum unclamped.
//
// pred:    [16384, 1024] f32
// centers: [10000, 1024] f32
// target:  [16384] int32
// out:     [1] f32

#define BATCH 16384
#define NUM_CLASSES 10000
#define FEAT_DIM 1024
#define THREADS 256
#define WARPS_PER_CTA (THREADS / 32)
#define ROWS_PER_WARP 2
#define GRID (BATCH / (WARPS_PER_CTA * ROWS_PER_WARP))   // 1024 CTAs -> single wave

__global__ void centerloss_init_kernel(float* out) {
    // masked-out entries contribute batch*(num_classes-1)*1e-12
    out[0] = (float)((double)BATCH * (double)(NUM_CLASSES - 1) * 1e-12);
}

__global__ __launch_bounds__(THREADS)
void centerloss_kernel(const float* __restrict__ pred,
                       const float* __restrict__ centers,
                       const int* __restrict__ target,
                       float* __restrict__ out) {
    const int tid  = threadIdx.x;
    const int wid  = tid >> 5;
    const int lane = tid & 31;
    // Warp w handles rows [base, base+ROWS_PER_WARP)
    const int base = (blockIdx.x * WARPS_PER_CTA + wid) * ROWS_PER_WARP;

    // Prefetch both class indices up front.
    int cls[ROWS_PER_WARP];
    #pragma unroll
    for (int r = 0; r < ROWS_PER_WARP; r++)
        cls[r] = __ldg(&target[base + r]);

    float acc = 0.0f;

    #pragma unroll
    for (int r = 0; r < ROWS_PER_WARP; r++) {
        const float4* p4 = reinterpret_cast<const float4*>(pred + (size_t)(base + r) * FEAT_DIM);
        const float4* c4 = reinterpret_cast<const float4*>(centers + (size_t)cls[r] * FEAT_DIM);

        // 1024 floats / warp-row = 8 float4 per lane, fully unrolled.
        float4 p[8], c[8];
        #pragma unroll
        for (int i = 0; i < 8; i++) p[i] = __ldcs(&p4[lane + 32 * i]);  // streaming: no reuse
        #pragma unroll
        for (int i = 0; i < 8; i++) c[i] = __ldg(&c4[lane + 32 * i]);   // L2-resident gather

        #pragma unroll
        for (int i = 0; i < 8; i++) {
            float d0 = p[i].x - c[i].x;
            float d1 = p[i].y - c[i].y;
            float d2 = p[i].z - c[i].z;
            float d3 = p[i].w - c[i].w;
            acc = fmaf(d0, d0, acc);
            acc = fmaf(d1, d1, acc);
            acc = fmaf(d2, d2, acc);
            acc = fmaf(d3, d3, acc);
        }
    }

    // Single end-of-kernel reduction: warp -> CTA -> one atomic per CTA.
    #pragma unroll
    for (int off = 16; off > 0; off >>= 1)
        acc += __shfl_xor_sync(0xFFFFFFFFu, acc, off);

    __shared__ float warp_sums[WARPS_PER_CTA];
    if (lane == 0) warp_sums[wid] = acc;
    __syncthreads();

    if (wid == 0) {
        float v = (lane < WARPS_PER_CTA) ? warp_sums[lane] : 0.0f;
        #pragma unroll
        for (int off = 4; off > 0; off >>= 1)
            v += __shfl_xor_sync(0xFFFFFFFFu, v, off);
        if (lane == 0)
            atomicAdd(out, v);
    }
}

extern "C" void kernel_launch(void* const* d_in, const int* in_sizes, int n_in,
                              void* d_out, int out_size) {
    // Identify inputs by element count (robust to metadata ordering).
    const float* pred    = nullptr;
    const float* centers = nullptr;
    const int*   target  = nullptr;
    for (int i = 0; i < n_in; i++) {
        if (in_sizes[i] == BATCH * FEAT_DIM)            pred    = (const float*)d_in[i];
        else if (in_sizes[i] == NUM_CLASSES * FEAT_DIM) centers = (const float*)d_in[i];
        else if (in_sizes[i] == BATCH)                  target  = (const int*)d_in[i];
    }
    float* out = (float*)d_out;

    centerloss_init_kernel<<<1, 1>>>(out);
    centerloss_kernel<<<GRID, THREADS>>>(pred, centers, target, out);
}